// round 3
// baseline (speedup 1.0000x reference)
#include <cuda_runtime.h>

#define BB 8
#define T 32768
#define R 64
#define S 128
#define NBLK 24
#define TT 128   // timestep tile per CTA

// Persistent scratch (allocation-free): ping-pong activation buffers + skip accumulator.
// Double-buffering h removes the intra-launch cross-CTA race (R2 bug: neighbor CTA's
// Phase-4 in-place h update was visible to this CTA's Phase-0 hp load).
__device__ __align__(16) float g_h[2][BB * R * T];   // 2 x 64 MB
__device__ __align__(16) float g_skip[BB * S * T];   // 128 MB

__device__ __forceinline__ void fma4(float4 &a, float w, const float4 &v) {
    a.x = fmaf(w, v.x, a.x);
    a.y = fmaf(w, v.y, a.y);
    a.z = fmaf(w, v.z, a.z);
    a.w = fmaf(w, v.w, a.w);
}

__device__ __forceinline__ float sigf(float x) { return 1.f / (1.f + expf(-x)); }

// ---------------------------------------------------------------------------
// Kernel 1: input 1x1 conv  h[b][r][t] = w_in[r] * x[b][t] + b_in[r]
// ---------------------------------------------------------------------------
__global__ void input_kernel(const float* __restrict__ x,
                             const float* __restrict__ w_in,
                             const float* __restrict__ b_in) {
    int idx = blockIdx.x * blockDim.x + threadIdx.x;   // [0, B*R*T)
    int t = idx & (T - 1);
    int r = (idx >> 15) & (R - 1);
    int b = idx >> 21;
    g_h[0][idx] = fmaf(__ldg(&w_in[r]), __ldg(&x[b * T + t]), __ldg(&b_in[r]));
}

// ---------------------------------------------------------------------------
// Kernel 2: one fused WaveNet block.
//   z = W0 h[t-d] + W1 h[t] + bc
//   a = tanh(Wf z + bf) * sigmoid(Wg z + bg)
//   skip (+)= Ws a + bs
//   h_out = h_in + Wr a + br     (ping-pong: h_in != h_out)
// Tile of TT=128 timesteps per CTA; h tiles + z + a live in smem.
// ---------------------------------------------------------------------------
__global__ void __launch_bounds__(256, 2) block_kernel(
    const float* __restrict__ h_in, float* __restrict__ h_out,
    const float* __restrict__ wc, const float* __restrict__ bc,
    const float* __restrict__ wf, const float* __restrict__ bf,
    const float* __restrict__ wg, const float* __restrict__ bg,
    const float* __restrict__ wr, const float* __restrict__ br,
    const float* __restrict__ ws, const float* __restrict__ bs,
    int d, int first)
{
    extern __shared__ float smem[];
    float* hn = smem;              // [R][TT] h at t
    float* hp = smem + R * TT;     // [R][TT] h at t-d; reused as 'a' after phase 2
    float* zz = smem + 2 * R * TT; // [R][TT] z

    const int b  = blockIdx.y;
    const int t0 = blockIdx.x * TT;
    const int tid = threadIdx.x;
    const int wp = tid >> 5, l = tid & 31;
    const float* hbase = h_in + (size_t)b * R * T;

    // ---- Phase 0: cooperative loads ----
    for (int f = tid; f < R * TT / 4; f += 256) {
        int row = f >> 5;            // TT/4 = 32 float4 per row
        int col = f & 31;
        ((float4*)hn)[f] = ((const float4*)(hbase + (size_t)row * T + t0))[col];
    }
    for (int idx = tid; idx < R * TT; idx += 256) {
        int row = idx >> 7;
        int col = idx & 127;
        int t = t0 + col - d;
        hp[idx] = (t >= 0) ? hbase[(size_t)row * T + t] : 0.f;
    }
    __syncthreads();

    const float4* hn4 = (const float4*)hn;
    const float4* hp4 = (const float4*)hp;
    float4* z4 = (float4*)zz;
    float4* a4 = (float4*)hp;   // reuse

    // ---- Phase 1: z = causal conv ----
    #pragma unroll
    for (int it = 0; it < 8; it += 2) {
        int coA = (wp << 3) + it, coB = coA + 1;
        const float2* wA = (const float2*)(wc + (coA << 7));  // [ci][k=2]
        const float2* wB = (const float2*)(wc + (coB << 7));
        float4 sA = {0,0,0,0}, sB = {0,0,0,0};
        #pragma unroll 8
        for (int ci = 0; ci < R; ci++) {
            float2 wa = __ldg(&wA[ci]);
            float2 wb = __ldg(&wB[ci]);
            float4 p = hp4[(ci << 5) + l];
            float4 n = hn4[(ci << 5) + l];
            fma4(sA, wa.x, p); fma4(sA, wa.y, n);
            fma4(sB, wb.x, p); fma4(sB, wb.y, n);
        }
        float bA = __ldg(&bc[coA]), bv = __ldg(&bc[coB]);
        z4[(coA << 5) + l] = make_float4(sA.x + bA, sA.y + bA, sA.z + bA, sA.w + bA);
        z4[(coB << 5) + l] = make_float4(sB.x + bv, sB.y + bv, sB.z + bv, sB.w + bv);
    }
    __syncthreads();

    // ---- Phase 2: a = tanh(Wf z + bf) * sigmoid(Wg z + bg) ----
    #pragma unroll
    for (int it = 0; it < 8; it += 2) {
        int coA = (wp << 3) + it, coB = coA + 1;
        const float* wfA = wf + (coA << 6); const float* wfB = wf + (coB << 6);
        const float* wgA = wg + (coA << 6); const float* wgB = wg + (coB << 6);
        float4 fA = {0,0,0,0}, fB = {0,0,0,0}, gA = {0,0,0,0}, gB = {0,0,0,0};
        #pragma unroll 8
        for (int ci = 0; ci < R; ci++) {
            float4 zv = z4[(ci << 5) + l];
            fma4(fA, __ldg(wfA + ci), zv);
            fma4(fB, __ldg(wfB + ci), zv);
            fma4(gA, __ldg(wgA + ci), zv);
            fma4(gB, __ldg(wgB + ci), zv);
        }
        float bfA = __ldg(bf + coA), bfB = __ldg(bf + coB);
        float bgA = __ldg(bg + coA), bgB = __ldg(bg + coB);
        float4 oA, oB;
        oA.x = tanhf(fA.x + bfA) * sigf(gA.x + bgA);
        oA.y = tanhf(fA.y + bfA) * sigf(gA.y + bgA);
        oA.z = tanhf(fA.z + bfA) * sigf(gA.z + bgA);
        oA.w = tanhf(fA.w + bfA) * sigf(gA.w + bgA);
        oB.x = tanhf(fB.x + bfB) * sigf(gB.x + bgB);
        oB.y = tanhf(fB.y + bfB) * sigf(gB.y + bgB);
        oB.z = tanhf(fB.z + bfB) * sigf(gB.z + bgB);
        oB.w = tanhf(fB.w + bfB) * sigf(gB.w + bgB);
        a4[(coA << 5) + l] = oA;
        a4[(coB << 5) + l] = oB;
    }
    __syncthreads();

    // ---- Phase 3: skip (+)= Ws a + bs ----
    {
        float* skp = g_skip + (size_t)b * S * T + t0;
        #pragma unroll
        for (int it = 0; it < 4; it++) {
            int s0 = (wp << 4) + (it << 2);
            float4 acc[4] = {{0,0,0,0},{0,0,0,0},{0,0,0,0},{0,0,0,0}};
            const float* w0 = ws + ((s0 + 0) << 6);
            const float* w1 = ws + ((s0 + 1) << 6);
            const float* w2 = ws + ((s0 + 2) << 6);
            const float* w3 = ws + ((s0 + 3) << 6);
            #pragma unroll 8
            for (int ci = 0; ci < R; ci++) {
                float4 av = a4[(ci << 5) + l];
                fma4(acc[0], __ldg(w0 + ci), av);
                fma4(acc[1], __ldg(w1 + ci), av);
                fma4(acc[2], __ldg(w2 + ci), av);
                fma4(acc[3], __ldg(w3 + ci), av);
            }
            #pragma unroll
            for (int j = 0; j < 4; j++) {
                int s = s0 + j;
                float bsv = __ldg(bs + s);
                float4 v = make_float4(acc[j].x + bsv, acc[j].y + bsv,
                                       acc[j].z + bsv, acc[j].w + bsv);
                float4* gp = (float4*)(skp + (size_t)s * T) + l;
                if (!first) {
                    float4 o = *gp;
                    v.x += o.x; v.y += o.y; v.z += o.z; v.w += o.w;
                }
                *gp = v;
            }
        }
    }

    // ---- Phase 4: h_out = h_in + Wr a + br ----
    {
        float* hdst = h_out + (size_t)b * R * T + t0;
        #pragma unroll
        for (int it = 0; it < 2; it++) {
            int c0 = (wp << 3) + (it << 2);
            float4 acc[4] = {{0,0,0,0},{0,0,0,0},{0,0,0,0},{0,0,0,0}};
            const float* w0 = wr + ((c0 + 0) << 6);
            const float* w1 = wr + ((c0 + 1) << 6);
            const float* w2 = wr + ((c0 + 2) << 6);
            const float* w3 = wr + ((c0 + 3) << 6);
            #pragma unroll 8
            for (int ci = 0; ci < R; ci++) {
                float4 av = a4[(ci << 5) + l];
                fma4(acc[0], __ldg(w0 + ci), av);
                fma4(acc[1], __ldg(w1 + ci), av);
                fma4(acc[2], __ldg(w2 + ci), av);
                fma4(acc[3], __ldg(w3 + ci), av);
            }
            #pragma unroll
            for (int j = 0; j < 4; j++) {
                int c = c0 + j;
                float brv = __ldg(br + c);
                float4 hv = hn4[(c << 5) + l];
                float4 v = make_float4(acc[j].x + brv + hv.x, acc[j].y + brv + hv.y,
                                       acc[j].z + brv + hv.z, acc[j].w + brv + hv.w);
                ((float4*)(hdst + (size_t)c * T))[l] = v;
            }
        }
    }
}

// ---------------------------------------------------------------------------
// Kernel 3: head.  out = W2 relu(W1 relu(skip) + b1) + b2
// ---------------------------------------------------------------------------
__global__ void __launch_bounds__(256) head_kernel(
    const float* __restrict__ w1, const float* __restrict__ b1,
    const float* __restrict__ w2, const float* __restrict__ b2,
    float* __restrict__ out)
{
    extern __shared__ float smem[];
    float* sk   = smem;            // [S][TT] relu(skip)
    float* part = smem + S * TT;   // [8][TT] per-warp partials

    const int b  = blockIdx.y;
    const int t0 = blockIdx.x * TT;
    const int tid = threadIdx.x, wp = tid >> 5, l = tid & 31;
    const float* skg = g_skip + (size_t)b * S * T + t0;

    for (int f = tid; f < S * TT / 4; f += 256) {
        int row = f >> 5, col = f & 31;
        float4 v = ((const float4*)(skg + (size_t)row * T))[col];
        v.x = fmaxf(v.x, 0.f); v.y = fmaxf(v.y, 0.f);
        v.z = fmaxf(v.z, 0.f); v.w = fmaxf(v.w, 0.f);
        ((float4*)sk)[f] = v;
    }
    __syncthreads();

    const float4* sk4 = (const float4*)sk;
    float4 po = {0,0,0,0};
    for (int s2 = wp * 16; s2 < wp * 16 + 16; s2++) {
        float4 u = {0,0,0,0};
        const float* wrow = w1 + (s2 << 7);
        #pragma unroll 8
        for (int s1 = 0; s1 < S; s1++)
            fma4(u, __ldg(wrow + s1), sk4[(s1 << 5) + l]);
        float bb = __ldg(b1 + s2);
        u.x = fmaxf(u.x + bb, 0.f); u.y = fmaxf(u.y + bb, 0.f);
        u.z = fmaxf(u.z + bb, 0.f); u.w = fmaxf(u.w + bb, 0.f);
        fma4(po, __ldg(w2 + s2), u);
    }
    ((float4*)(part + wp * TT))[l] = po;
    __syncthreads();

    if (tid < TT) {
        float acc = __ldg(b2);
        #pragma unroll
        for (int ww = 0; ww < 8; ww++) acc += part[ww * TT + tid];
        out[(size_t)b * T + t0 + tid] = acc;   // output layout [B, T, 1]
    }
}

// ---------------------------------------------------------------------------
extern "C" void kernel_launch(void* const* d_in, const int* in_sizes, int n_in,
                              void* d_out, int out_size) {
    const float* x        = (const float*)d_in[0];
    const float* w_in     = (const float*)d_in[1];
    const float* b_in     = (const float*)d_in[2];
    const float* w_causal = (const float*)d_in[3];
    const float* b_causal = (const float*)d_in[4];
    const float* w_filter = (const float*)d_in[5];
    const float* b_filter = (const float*)d_in[6];
    const float* w_gate   = (const float*)d_in[7];
    const float* b_gate   = (const float*)d_in[8];
    const float* w_res    = (const float*)d_in[9];
    const float* b_res    = (const float*)d_in[10];
    const float* w_skip   = (const float*)d_in[11];
    const float* b_skip   = (const float*)d_in[12];
    const float* w_out1   = (const float*)d_in[13];
    const float* b_out1   = (const float*)d_in[14];
    const float* w_out2   = (const float*)d_in[15];
    const float* b_out2   = (const float*)d_in[16];
    float* out = (float*)d_out;

    const int blk_smem  = 3 * R * TT * 4;            // 96 KB
    const int head_smem = (S * TT + 8 * TT) * 4;     // 68 KB
    cudaFuncSetAttribute(block_kernel, cudaFuncAttributeMaxDynamicSharedMemorySize, blk_smem);
    cudaFuncSetAttribute(head_kernel,  cudaFuncAttributeMaxDynamicSharedMemorySize, head_smem);

    input_kernel<<<BB * R * T / 256, 256>>>(x, w_in, b_in);

    float* hbuf[2];
    cudaGetSymbolAddress((void**)&hbuf[0], g_h);
    hbuf[1] = hbuf[0] + (size_t)BB * R * T;

    dim3 grid(T / TT, BB);
    for (int i = 0; i < NBLK; i++) {
        int d = 1 << (i & 7);   // dilations 1..128, repeated 3x
        block_kernel<<<grid, 256, blk_smem>>>(
            hbuf[i & 1], hbuf[(i + 1) & 1],
            w_causal + (size_t)i * R * R * 2, b_causal + (size_t)i * R,
            w_filter + (size_t)i * R * R,     b_filter + (size_t)i * R,
            w_gate   + (size_t)i * R * R,     b_gate   + (size_t)i * R,
            w_res    + (size_t)i * R * R,     b_res    + (size_t)i * R,
            w_skip   + (size_t)i * S * R,     b_skip   + (size_t)i * S,
            d, i == 0 ? 1 : 0);
    }

    head_kernel<<<grid, 256, head_smem>>>(w_out1, b_out1, w_out2, b_out2, out);
}

// round 4
// speedup vs baseline: 1.1668x; 1.1668x over previous
#include <cuda_runtime.h>

#define BB 8
#define T 32768
#define R 64
#define S 128
#define NBLK 24
#define TT 128   // timestep tile per CTA

// Persistent scratch (allocation-free): ping-pong h + skip accumulator + transposed weights.
__device__ __align__(16) float g_h[2][BB * R * T];   // 2 x 64 MB
__device__ __align__(16) float g_skip[BB * S * T];   // 128 MB
// Transposed weights, built once per launch by prep_kernel:
//   g_wcT [l][ci][k][co]      (row = 128 floats: k=0 prev-tap 64 co, k=1 cur-tap 64 co)
//   g_wfg [l][ci][co']        (co'<64: filter, co'>=64: gate)
//   g_wrs [l][ci][co']        (co'<64: res,    co'>=64: skip (128))
__device__ __align__(16) float g_wcT[NBLK * R * 128];
__device__ __align__(16) float g_wfg[NBLK * R * 128];
__device__ __align__(16) float g_wrs[NBLK * R * 192];

#define PRE1 (NBLK * R * 128)
#define PRE2 (NBLK * R * 128)
#define PRE3 (NBLK * R * 192)

__device__ __forceinline__ void fma4(float4 &a, float w, const float4 &v) {
    a.x = fmaf(w, v.x, a.x);
    a.y = fmaf(w, v.y, a.y);
    a.z = fmaf(w, v.z, a.z);
    a.w = fmaf(w, v.w, a.w);
}

__device__ __forceinline__ float sigf(float x) { return 1.f / (1.f + expf(-x)); }

// ---------------------------------------------------------------------------
// Prep: build transposed weight layouts (runs once per launch; ~0.7M elems)
// ---------------------------------------------------------------------------
__global__ void prep_kernel(const float* __restrict__ wc, const float* __restrict__ wf,
                            const float* __restrict__ wg, const float* __restrict__ wr,
                            const float* __restrict__ ws) {
    int idx = blockIdx.x * blockDim.x + threadIdx.x;
    if (idx < PRE1) {
        int l = idx >> 13, r = idx & 8191;
        int ci = r >> 7, k = (r >> 6) & 1, co = r & 63;
        g_wcT[idx] = wc[(((size_t)l * 64 + co) * 64 + ci) * 2 + k];
        return;
    }
    idx -= PRE1;
    if (idx < PRE2) {
        int l = idx >> 13, r = idx & 8191;
        int ci = r >> 7, cp = r & 127;
        g_wfg[idx] = (cp < 64) ? wf[((size_t)l * 64 + cp) * 64 + ci]
                               : wg[((size_t)l * 64 + cp - 64) * 64 + ci];
        return;
    }
    idx -= PRE2;
    if (idx < PRE3) {
        int l = idx / (64 * 192), r = idx % (64 * 192);
        int ci = r / 192, cp = r % 192;
        g_wrs[idx] = (cp < 64) ? wr[((size_t)l * 64 + cp) * 64 + ci]
                               : ws[((size_t)l * 128 + cp - 64) * 64 + ci];
    }
}

// ---------------------------------------------------------------------------
// Kernel 1: input 1x1 conv  h[b][r][t] = w_in[r] * x[b][t] + b_in[r]
// ---------------------------------------------------------------------------
__global__ void input_kernel(const float* __restrict__ x,
                             const float* __restrict__ w_in,
                             const float* __restrict__ b_in) {
    int idx = blockIdx.x * blockDim.x + threadIdx.x;   // [0, B*R*T)
    int t = idx & (T - 1);
    int r = (idx >> 15) & (R - 1);
    int b = idx >> 21;
    g_h[0][idx] = fmaf(__ldg(&w_in[r]), __ldg(&x[b * T + t]), __ldg(&b_in[r]));
}

// ---------------------------------------------------------------------------
// Kernel 2: one fused WaveNet block (transposed weights, 8-12 co register tiles).
// ---------------------------------------------------------------------------
__global__ void __launch_bounds__(256, 2) block_kernel(
    const float* __restrict__ h_in, float* __restrict__ h_out,
    const float* __restrict__ wcT, const float* __restrict__ bc,
    const float* __restrict__ wfg, const float* __restrict__ bf,
    const float* __restrict__ bg,
    const float* __restrict__ wrs, const float* __restrict__ br,
    const float* __restrict__ bs,
    int d, int first)
{
    extern __shared__ float smem[];
    float* hn = smem;              // [R][TT] h at t
    float* hp = smem + R * TT;     // [R][TT] h at t-d; reused as 'a' after phase 2
    float* zz = smem + 2 * R * TT; // [R][TT] z

    const int b  = blockIdx.y;
    const int t0 = blockIdx.x * TT;
    const int tid = threadIdx.x;
    const int wp = tid >> 5, l = tid & 31;
    const float* hbase = h_in + (size_t)b * R * T;

    // ---- Phase 0: cooperative loads ----
    for (int f = tid; f < R * TT / 4; f += 256) {
        int row = f >> 5;            // TT/4 = 32 float4 per row
        int col = f & 31;
        ((float4*)hn)[f] = ((const float4*)(hbase + (size_t)row * T + t0))[col];
    }
    if ((d & 3) == 0) {
        const int dq = d >> 2;
        for (int f = tid; f < R * 32; f += 256) {
            int row = f >> 5, col = f & 31;
            int tq = (t0 >> 2) + col - dq;
            float4 v = (tq >= 0) ? ((const float4*)(hbase + (size_t)row * T))[tq]
                                 : make_float4(0.f, 0.f, 0.f, 0.f);
            ((float4*)hp)[f] = v;
        }
    } else {
        for (int idx = tid; idx < R * TT; idx += 256) {
            int row = idx >> 7;
            int col = idx & 127;
            int t = t0 + col - d;
            hp[idx] = (t >= 0) ? hbase[(size_t)row * T + t] : 0.f;
        }
    }
    __syncthreads();

    const float4* hn4 = (const float4*)hn;
    const float4* hp4 = (const float4*)hp;
    float4* z4 = (float4*)zz;
    float4* a4 = (float4*)hp;   // reuse

    const int wco = wp << 1;    // this warp's 8-co block as float4 offset

    // ---- Phase 1: z = causal conv (8 co per warp, weights [ci][k][co]) ----
    {
        const float4* wc4 = (const float4*)wcT;
        float4 acc[8];
        #pragma unroll
        for (int j = 0; j < 8; j++) acc[j] = make_float4(0.f, 0.f, 0.f, 0.f);
        #pragma unroll 4
        for (int ci = 0; ci < R; ci++) {
            float4 p  = hp4[(ci << 5) + l];
            float4 n  = hn4[(ci << 5) + l];
            float4 w0 = __ldg(&wc4[ci * 32 + wco]);          // prev tap, co0..3
            float4 w1 = __ldg(&wc4[ci * 32 + wco + 1]);      // prev tap, co4..7
            float4 w2 = __ldg(&wc4[ci * 32 + 16 + wco]);     // cur tap,  co0..3
            float4 w3 = __ldg(&wc4[ci * 32 + 16 + wco + 1]); // cur tap,  co4..7
            fma4(acc[0], w0.x, p); fma4(acc[1], w0.y, p);
            fma4(acc[2], w0.z, p); fma4(acc[3], w0.w, p);
            fma4(acc[4], w1.x, p); fma4(acc[5], w1.y, p);
            fma4(acc[6], w1.z, p); fma4(acc[7], w1.w, p);
            fma4(acc[0], w2.x, n); fma4(acc[1], w2.y, n);
            fma4(acc[2], w2.z, n); fma4(acc[3], w2.w, n);
            fma4(acc[4], w3.x, n); fma4(acc[5], w3.y, n);
            fma4(acc[6], w3.z, n); fma4(acc[7], w3.w, n);
        }
        #pragma unroll
        for (int j = 0; j < 8; j++) {
            int co = (wp << 3) + j;
            float bv = __ldg(&bc[co]);
            z4[(co << 5) + l] = make_float4(acc[j].x + bv, acc[j].y + bv,
                                            acc[j].z + bv, acc[j].w + bv);
        }
    }
    __syncthreads();

    // ---- Phase 2: a = tanh(Wf z + bf) * sigmoid(Wg z + bg)  (8 co, f+g together) ----
    {
        const float4* w4 = (const float4*)wfg;
        float4 af[8], ag[8];
        #pragma unroll
        for (int j = 0; j < 8; j++) {
            af[j] = make_float4(0.f, 0.f, 0.f, 0.f);
            ag[j] = make_float4(0.f, 0.f, 0.f, 0.f);
        }
        #pragma unroll 4
        for (int ci = 0; ci < R; ci++) {
            float4 zv = z4[(ci << 5) + l];
            float4 f0 = __ldg(&w4[ci * 32 + wco]);
            float4 f1 = __ldg(&w4[ci * 32 + wco + 1]);
            float4 g0 = __ldg(&w4[ci * 32 + 16 + wco]);
            float4 g1 = __ldg(&w4[ci * 32 + 16 + wco + 1]);
            fma4(af[0], f0.x, zv); fma4(af[1], f0.y, zv);
            fma4(af[2], f0.z, zv); fma4(af[3], f0.w, zv);
            fma4(af[4], f1.x, zv); fma4(af[5], f1.y, zv);
            fma4(af[6], f1.z, zv); fma4(af[7], f1.w, zv);
            fma4(ag[0], g0.x, zv); fma4(ag[1], g0.y, zv);
            fma4(ag[2], g0.z, zv); fma4(ag[3], g0.w, zv);
            fma4(ag[4], g1.x, zv); fma4(ag[5], g1.y, zv);
            fma4(ag[6], g1.z, zv); fma4(ag[7], g1.w, zv);
        }
        __syncthreads();   // everyone done reading z & hp before a overwrites hp
        #pragma unroll
        for (int j = 0; j < 8; j++) {
            int co = (wp << 3) + j;
            float bfv = __ldg(&bf[co]);
            float bgv = __ldg(&bg[co]);
            float4 o;
            o.x = tanhf(af[j].x + bfv) * sigf(ag[j].x + bgv);
            o.y = tanhf(af[j].y + bfv) * sigf(ag[j].y + bgv);
            o.z = tanhf(af[j].z + bfv) * sigf(ag[j].z + bgv);
            o.w = tanhf(af[j].w + bfv) * sigf(ag[j].w + bgv);
            a4[(co << 5) + l] = o;
        }
    }
    __syncthreads();

    // ---- Phase 3: fused res + skip over 192 transposed rows (12 co x 2 chunks/warp) ----
    {
        const float4* w4 = (const float4*)wrs;
        float* hdst = h_out + (size_t)b * R * T + t0;
        float* skp  = g_skip + (size_t)b * S * T + t0;
        #pragma unroll
        for (int chunk = 0; chunk < 2; chunk++) {
            const int co0 = wp * 24 + chunk * 12;      // 12 consecutive co'
            const int wq  = (co0 >> 2);                // float4 offset within 48-wide row
            float4 acc[12];
            #pragma unroll
            for (int j = 0; j < 12; j++) acc[j] = make_float4(0.f, 0.f, 0.f, 0.f);
            #pragma unroll 4
            for (int ci = 0; ci < R; ci++) {
                float4 av = a4[(ci << 5) + l];
                float4 w0 = __ldg(&w4[ci * 48 + wq]);
                float4 w1 = __ldg(&w4[ci * 48 + wq + 1]);
                float4 w2 = __ldg(&w4[ci * 48 + wq + 2]);
                fma4(acc[0], w0.x, av); fma4(acc[1],  w0.y, av);
                fma4(acc[2], w0.z, av); fma4(acc[3],  w0.w, av);
                fma4(acc[4], w1.x, av); fma4(acc[5],  w1.y, av);
                fma4(acc[6], w1.z, av); fma4(acc[7],  w1.w, av);
                fma4(acc[8], w2.x, av); fma4(acc[9],  w2.y, av);
                fma4(acc[10], w2.z, av); fma4(acc[11], w2.w, av);
            }
            #pragma unroll
            for (int j = 0; j < 12; j++) {
                int cp = co0 + j;
                if (cp < 64) {
                    // residual: h_out = h_in + Wr a + br
                    float bv = __ldg(&br[cp]);
                    float4 hv = hn4[(cp << 5) + l];
                    float4 v = make_float4(acc[j].x + bv + hv.x, acc[j].y + bv + hv.y,
                                           acc[j].z + bv + hv.z, acc[j].w + bv + hv.w);
                    ((float4*)(hdst + (size_t)cp * T))[l] = v;
                } else {
                    int s = cp - 64;
                    float bv = __ldg(&bs[s]);
                    float4 v = make_float4(acc[j].x + bv, acc[j].y + bv,
                                           acc[j].z + bv, acc[j].w + bv);
                    float4* gp = (float4*)(skp + (size_t)s * T) + l;
                    if (!first) {
                        float4 o = *gp;
                        v.x += o.x; v.y += o.y; v.z += o.z; v.w += o.w;
                    }
                    *gp = v;
                }
            }
        }
    }
}

// ---------------------------------------------------------------------------
// Kernel 3: head.  out = W2 relu(W1 relu(skip) + b1) + b2
// ---------------------------------------------------------------------------
__global__ void __launch_bounds__(256) head_kernel(
    const float* __restrict__ w1, const float* __restrict__ b1,
    const float* __restrict__ w2, const float* __restrict__ b2,
    float* __restrict__ out)
{
    extern __shared__ float smem[];
    float* sk   = smem;            // [S][TT] relu(skip)
    float* part = smem + S * TT;   // [8][TT] per-warp partials

    const int b  = blockIdx.y;
    const int t0 = blockIdx.x * TT;
    const int tid = threadIdx.x, wp = tid >> 5, l = tid & 31;
    const float* skg = g_skip + (size_t)b * S * T + t0;

    for (int f = tid; f < S * TT / 4; f += 256) {
        int row = f >> 5, col = f & 31;
        float4 v = ((const float4*)(skg + (size_t)row * T))[col];
        v.x = fmaxf(v.x, 0.f); v.y = fmaxf(v.y, 0.f);
        v.z = fmaxf(v.z, 0.f); v.w = fmaxf(v.w, 0.f);
        ((float4*)sk)[f] = v;
    }
    __syncthreads();

    const float4* sk4 = (const float4*)sk;
    float4 po = {0.f, 0.f, 0.f, 0.f};
    for (int s2 = wp * 16; s2 < wp * 16 + 16; s2++) {
        float4 u = {0.f, 0.f, 0.f, 0.f};
        const float* wrow = w1 + (s2 << 7);
        #pragma unroll 8
        for (int s1 = 0; s1 < S; s1++)
            fma4(u, __ldg(wrow + s1), sk4[(s1 << 5) + l]);
        float bb = __ldg(b1 + s2);
        u.x = fmaxf(u.x + bb, 0.f); u.y = fmaxf(u.y + bb, 0.f);
        u.z = fmaxf(u.z + bb, 0.f); u.w = fmaxf(u.w + bb, 0.f);
        fma4(po, __ldg(w2 + s2), u);
    }
    ((float4*)(part + wp * TT))[l] = po;
    __syncthreads();

    if (tid < TT) {
        float acc = __ldg(b2);
        #pragma unroll
        for (int ww = 0; ww < 8; ww++) acc += part[ww * TT + tid];
        out[(size_t)b * T + t0 + tid] = acc;   // output layout [B, T, 1]
    }
}

// ---------------------------------------------------------------------------
extern "C" void kernel_launch(void* const* d_in, const int* in_sizes, int n_in,
                              void* d_out, int out_size) {
    const float* x        = (const float*)d_in[0];
    const float* w_in     = (const float*)d_in[1];
    const float* b_in     = (const float*)d_in[2];
    const float* w_causal = (const float*)d_in[3];
    const float* b_causal = (const float*)d_in[4];
    const float* w_filter = (const float*)d_in[5];
    const float* b_filter = (const float*)d_in[6];
    const float* w_gate   = (const float*)d_in[7];
    const float* b_gate   = (const float*)d_in[8];
    const float* w_res    = (const float*)d_in[9];
    const float* b_res    = (const float*)d_in[10];
    const float* w_skip   = (const float*)d_in[11];
    const float* b_skip   = (const float*)d_in[12];
    const float* w_out1   = (const float*)d_in[13];
    const float* b_out1   = (const float*)d_in[14];
    const float* w_out2   = (const float*)d_in[15];
    const float* b_out2   = (const float*)d_in[16];
    float* out = (float*)d_out;

    const int blk_smem  = 3 * R * TT * 4;            // 96 KB
    const int head_smem = (S * TT + 8 * TT) * 4;     // 68 KB
    cudaFuncSetAttribute(block_kernel, cudaFuncAttributeMaxDynamicSharedMemorySize, blk_smem);
    cudaFuncSetAttribute(head_kernel,  cudaFuncAttributeMaxDynamicSharedMemorySize, head_smem);

    float* hbuf0; float* wct; float* wfg; float* wrs;
    cudaGetSymbolAddress((void**)&hbuf0, g_h);
    cudaGetSymbolAddress((void**)&wct, g_wcT);
    cudaGetSymbolAddress((void**)&wfg, g_wfg);
    cudaGetSymbolAddress((void**)&wrs, g_wrs);
    float* hbuf[2] = { hbuf0, hbuf0 + (size_t)BB * R * T };

    const int pre_total = PRE1 + PRE2 + PRE3;
    prep_kernel<<<(pre_total + 255) / 256, 256>>>(w_causal, w_filter, w_gate, w_res, w_skip);

    input_kernel<<<BB * R * T / 256, 256>>>(x, w_in, b_in);

    dim3 grid(T / TT, BB);
    for (int i = 0; i < NBLK; i++) {
        int d = 1 << (i & 7);   // dilations 1..128, repeated 3x
        block_kernel<<<grid, 256, blk_smem>>>(
            hbuf[i & 1], hbuf[(i + 1) & 1],
            wct + (size_t)i * R * 128, b_causal + (size_t)i * R,
            wfg + (size_t)i * R * 128, b_filter + (size_t)i * R, b_gate + (size_t)i * R,
            wrs + (size_t)i * R * 192, b_res + (size_t)i * R, b_skip + (size_t)i * S,
            d, i == 0 ? 1 : 0);
    }

    head_kernel<<<grid, 256, head_smem>>>(w_out1, b_out1, w_out2, b_out2, out);
}